// round 1
// baseline (speedup 1.0000x reference)
#include <cuda_runtime.h>
#include <cuda_bf16.h>
#include <cstdint>

// ---------------------------------------------------------------------------
// FCHCGNN: 3-layer GCN.
//   deg/norm: deg[i] = 1 + #edges with dst==i ; dis = rsqrt(deg)
//   per layer: H = relu_in(X) @ W ; AGG = b ; AGG[dst] += H[src]*dis[src]*dis[dst]
//              (+ self loop  AGG[i] += H[i]*dis[i]^2)
//   final: out = log_softmax(relu(AGG2))
// ---------------------------------------------------------------------------

#define MAXN 100000
#define FDIM 128

__device__ float g_h[(size_t)MAXN * FDIM];    // GEMM output (messages source)
__device__ float g_agg[(size_t)MAXN * FDIM];  // aggregation buffer
__device__ float g_dis[MAXN];                 // deg -> rsqrt(deg)

// ------------------------------- degree ------------------------------------
__global__ void k_deg_init(int n) {
    int i = blockIdx.x * blockDim.x + threadIdx.x;
    if (i < n) g_dis[i] = 1.0f;  // self loop contributes 1
}

__global__ void k_deg_count(const int* __restrict__ dst, int E) {
    int e = blockIdx.x * blockDim.x + threadIdx.x;
    if (e < E) atomicAdd(&g_dis[dst[e]], 1.0f);
}

__global__ void k_deg_rsqrt(int n) {
    int i = blockIdx.x * blockDim.x + threadIdx.x;
    if (i < n) g_dis[i] = rsqrtf(g_dis[i]);
}

// ------------------------------- GEMM ---------------------------------------
// H[M,BN] = relu?(X[M,128]) @ W[128,BN].  BM=128, BK=8, TM=8.
// BN=128,TN=8 or BN=64,TN=4 -> 256 threads either way.
template <int BN, int TN, bool FROM_AGG>
__global__ void k_gemm(const float* __restrict__ Xin, const float* __restrict__ W, int M) {
    constexpr int BM = 128, BK = 8, TM = 8, K = 128;
    __shared__ float As[BK * BM];
    __shared__ float Bs[BK * BN];

    const float* __restrict__ X = FROM_AGG ? g_agg : Xin;

    const int tid = threadIdx.x;
    const int br = blockIdx.x * BM;
    const int tCol = tid % (BN / TN);
    const int tRow = tid / (BN / TN);

    const int aRow = tid >> 1;       // 0..127
    const int aSeg = tid & 1;        // which float4 of the 8-wide k-slice

    float acc[TM][TN];
#pragma unroll
    for (int i = 0; i < TM; i++)
#pragma unroll
        for (int j = 0; j < TN; j++) acc[i][j] = 0.0f;

    for (int k0 = 0; k0 < K; k0 += BK) {
        // ---- load A tile (128 rows x 8 k), transposed into As[k][m]
        float4 a = make_float4(0.f, 0.f, 0.f, 0.f);
        int gr = br + aRow;
        if (gr < M) a = *(const float4*)(X + (size_t)gr * K + k0 + aSeg * 4);
        if (FROM_AGG) {
            a.x = fmaxf(a.x, 0.f); a.y = fmaxf(a.y, 0.f);
            a.z = fmaxf(a.z, 0.f); a.w = fmaxf(a.w, 0.f);
        }
        As[(aSeg * 4 + 0) * BM + aRow] = a.x;
        As[(aSeg * 4 + 1) * BM + aRow] = a.y;
        As[(aSeg * 4 + 2) * BM + aRow] = a.z;
        As[(aSeg * 4 + 3) * BM + aRow] = a.w;

        // ---- load B tile (8 k x BN)
        if (BN == 128 || tid < (BK * BN / 4)) {
            int bRow = tid / (BN / 4);
            int bCol = (tid % (BN / 4)) * 4;
            float4 b = *(const float4*)(W + (size_t)(k0 + bRow) * BN + bCol);
            *(float4*)&Bs[bRow * BN + bCol] = b;
        }
        __syncthreads();

#pragma unroll
        for (int kk = 0; kk < BK; kk++) {
            float ra[TM], rb[TN];
#pragma unroll
            for (int i = 0; i < TM; i++) ra[i] = As[kk * BM + tRow * TM + i];
#pragma unroll
            for (int j = 0; j < TN; j++) rb[j] = Bs[kk * BN + tCol * TN + j];
#pragma unroll
            for (int i = 0; i < TM; i++)
#pragma unroll
                for (int j = 0; j < TN; j++) acc[i][j] += ra[i] * rb[j];
        }
        __syncthreads();
    }

#pragma unroll
    for (int i = 0; i < TM; i++) {
        int gr = br + tRow * TM + i;
        if (gr < M) {
            float* out = g_h + (size_t)gr * BN + tCol * TN;
#pragma unroll
            for (int j = 0; j < TN; j++) out[j] = acc[i][j];
        }
    }
}

// --------------------------- agg init (bias) --------------------------------
template <int F>
__global__ void k_agg_init(const float* __restrict__ b, int M) {
    size_t idx = (size_t)blockIdx.x * blockDim.x + threadIdx.x;
    size_t total = (size_t)M * F;
    if (idx < total) g_agg[idx] = b[idx % F];
}

// ------------------------------- scatter ------------------------------------
__device__ __forceinline__ void red_add4(float* p, float a, float b, float c, float d) {
    asm volatile("red.global.add.v4.f32 [%0], {%1,%2,%3,%4};"
                 :: "l"(p), "f"(a), "f"(b), "f"(c), "f"(d) : "memory");
}
__device__ __forceinline__ void red_add2(float* p, float a, float b) {
    asm volatile("red.global.add.v2.f32 [%0], {%1,%2};"
                 :: "l"(p), "f"(a), "f"(b) : "memory");
}

// one warp per (edge or self-loop)
template <int F>
__global__ void k_scatter(const int* __restrict__ src, const int* __restrict__ dst,
                          int E, int n) {
    int w = (int)(((size_t)blockIdx.x * blockDim.x + threadIdx.x) >> 5);
    int lane = threadIdx.x & 31;
    if (w >= E + n) return;

    int s, d;
    float nrm;
    if (w < E) {
        s = src[w];
        d = dst[w];
        nrm = g_dis[s] * g_dis[d];
    } else {
        s = d = w - E;
        float t = g_dis[s];
        nrm = t * t;
    }

    if (F == 128) {
        const float4* h4 = (const float4*)(g_h + (size_t)s * 128);
        float4 v = h4[lane];
        red_add4(g_agg + (size_t)d * 128 + lane * 4,
                 v.x * nrm, v.y * nrm, v.z * nrm, v.w * nrm);
    } else {  // F == 64
        const float2* h2 = (const float2*)(g_h + (size_t)s * 64);
        float2 v = h2[lane];
        red_add2(g_agg + (size_t)d * 64 + lane * 2, v.x * nrm, v.y * nrm);
    }
}

// --------------------- relu + log_softmax over 64 cols ----------------------
__global__ void k_logsoftmax64(float* __restrict__ out, int M) {
    int w = (int)(((size_t)blockIdx.x * blockDim.x + threadIdx.x) >> 5);
    int lane = threadIdx.x & 31;
    if (w >= M) return;

    const float2* row = (const float2*)(g_agg + (size_t)w * 64);
    float2 v = row[lane];
    v.x = fmaxf(v.x, 0.f);
    v.y = fmaxf(v.y, 0.f);

    float m = fmaxf(v.x, v.y);
#pragma unroll
    for (int off = 16; off; off >>= 1) m = fmaxf(m, __shfl_xor_sync(0xFFFFFFFFu, m, off));

    float ssum = expf(v.x - m) + expf(v.y - m);
#pragma unroll
    for (int off = 16; off; off >>= 1) ssum += __shfl_xor_sync(0xFFFFFFFFu, ssum, off);

    float l = logf(ssum);
    float2 o;
    o.x = v.x - m - l;
    o.y = v.y - m - l;
    ((float2*)(out + (size_t)w * 64))[lane] = o;
}

// ----------------------------------------------------------------------------
extern "C" void kernel_launch(void* const* d_in, const int* in_sizes, int n_in,
                              void* d_out, int out_size) {
    const float* x  = (const float*)d_in[0];
    const int* ei   = (const int*)d_in[1];
    const float* W0 = (const float*)d_in[2];
    const float* b0 = (const float*)d_in[3];
    const float* W1 = (const float*)d_in[4];
    const float* b1 = (const float*)d_in[5];
    const float* W2 = (const float*)d_in[6];
    const float* b2 = (const float*)d_in[7];
    float* out = (float*)d_out;

    const int N = in_sizes[0] / 128;
    const int E = in_sizes[1] / 2;
    const int* src = ei;
    const int* dst = ei + E;

    const int T = 256;

    // degree / normalization
    k_deg_init<<<(N + T - 1) / T, T>>>(N);
    k_deg_count<<<(E + T - 1) / T, T>>>(dst, E);
    k_deg_rsqrt<<<(N + T - 1) / T, T>>>(N);

    const int gemmBlocks = (N + 127) / 128;
    const int scatWarps = E + N;
    const int scatBlocks = (scatWarps * 32 + T - 1) / T;

    // ---- layer 0: 128 -> 128
    k_gemm<128, 8, false><<<gemmBlocks, 256>>>(x, W0, N);
    {
        size_t total = (size_t)N * 128;
        k_agg_init<128><<<(int)((total + T - 1) / T), T>>>(b0, N);
    }
    k_scatter<128><<<scatBlocks, T>>>(src, dst, E, N);

    // ---- layer 1: 128 -> 128 (relu fused into A load)
    k_gemm<128, 8, true><<<gemmBlocks, 256>>>(nullptr, W1, N);
    {
        size_t total = (size_t)N * 128;
        k_agg_init<128><<<(int)((total + T - 1) / T), T>>>(b1, N);
    }
    k_scatter<128><<<scatBlocks, T>>>(src, dst, E, N);

    // ---- layer 2: 128 -> 64
    k_gemm<64, 4, true><<<gemmBlocks, 256>>>(nullptr, W2, N);
    {
        size_t total = (size_t)N * 64;
        k_agg_init<64><<<(int)((total + T - 1) / T), T>>>(b2, N);
    }
    k_scatter<64><<<scatBlocks, T>>>(src, dst, E, N);

    // ---- relu + log_softmax -> out
    k_logsoftmax64<<<(N * 32 + T - 1) / T, T>>>(out, N);
}

// round 2
// speedup vs baseline: 1.4764x; 1.4764x over previous
#include <cuda_runtime.h>
#include <cuda_bf16.h>
#include <cstdint>

// ---------------------------------------------------------------------------
// FCHCGNN: 3-layer GCN, CSR gather formulation (no float atomics).
// ---------------------------------------------------------------------------

#define MAXN 100000
#define MAXE 1600000
#define FDIM 128

__device__ float g_h[(size_t)MAXN * FDIM];    // GEMM output (message source)
__device__ float g_agg[(size_t)MAXN * FDIM];  // aggregation buffer
__device__ float g_dis[MAXN];                 // rsqrt(deg)
__device__ int   g_cnt[MAXN];                 // in-degree counts
__device__ int   g_cur[MAXN];                 // fill cursors
__device__ int   g_rowptr[MAXN + 1];          // CSR row pointers (by dst)
__device__ int   g_esrc[MAXE];                // CSR: src node per slot

// ------------------------------- degree ------------------------------------
__global__ void k_deg_init(int n) {
    int i = blockIdx.x * blockDim.x + threadIdx.x;
    if (i < n) { g_dis[i] = 1.0f; g_cnt[i] = 0; g_cur[i] = 0; }
}

__global__ void k_deg_count(const int* __restrict__ dst, int E) {
    int e = blockIdx.x * blockDim.x + threadIdx.x;
    if (e < E) {
        int d = dst[e];
        atomicAdd(&g_dis[d], 1.0f);
        atomicAdd(&g_cnt[d], 1);
    }
}

__global__ void k_deg_rsqrt(int n) {
    int i = blockIdx.x * blockDim.x + threadIdx.x;
    if (i < n) g_dis[i] = rsqrtf(g_dis[i]);
}

// ----------------------- exclusive scan (single block) ----------------------
__global__ void k_scan(int n) {
    __shared__ int sh[1024];
    __shared__ int carry;
    const int tid = threadIdx.x;
    if (tid == 0) carry = 0;
    __syncthreads();
    for (int base = 0; base < n; base += 1024) {
        int i = base + tid;
        int v = (i < n) ? g_cnt[i] : 0;
        sh[tid] = v;
        __syncthreads();
#pragma unroll
        for (int off = 1; off < 1024; off <<= 1) {
            int t = (tid >= off) ? sh[tid - off] : 0;
            __syncthreads();
            sh[tid] += t;
            __syncthreads();
        }
        if (i < n) g_rowptr[i] = carry + sh[tid] - v;   // exclusive
        __syncthreads();
        if (tid == 0) carry += sh[1023];
        __syncthreads();
    }
    if (tid == 0) g_rowptr[n] = carry;
}

// ------------------------------ CSR fill ------------------------------------
__global__ void k_fill(const int* __restrict__ src, const int* __restrict__ dst, int E) {
    int e = blockIdx.x * blockDim.x + threadIdx.x;
    if (e < E) {
        int d = dst[e];
        int pos = g_rowptr[d] + atomicAdd(&g_cur[d], 1);
        g_esrc[pos] = src[e];
    }
}

// ------------------------------- GEMM ---------------------------------------
// H[M,BN] = relu?(X[M,128]) @ W[128,BN].  BM=128, BK=8, TM=8.
template <int BN, int TN, bool FROM_AGG>
__global__ void k_gemm(const float* __restrict__ Xin, const float* __restrict__ W, int M) {
    constexpr int BM = 128, BK = 8, TM = 8, K = 128;
    __shared__ float As[BK * BM];
    __shared__ float Bs[BK * BN];

    const float* __restrict__ X = FROM_AGG ? g_agg : Xin;

    const int tid = threadIdx.x;
    const int br = blockIdx.x * BM;
    const int tCol = tid % (BN / TN);
    const int tRow = tid / (BN / TN);

    const int aRow = tid >> 1;
    const int aSeg = tid & 1;

    float acc[TM][TN];
#pragma unroll
    for (int i = 0; i < TM; i++)
#pragma unroll
        for (int j = 0; j < TN; j++) acc[i][j] = 0.0f;

    for (int k0 = 0; k0 < K; k0 += BK) {
        float4 a = make_float4(0.f, 0.f, 0.f, 0.f);
        int gr = br + aRow;
        if (gr < M) a = *(const float4*)(X + (size_t)gr * K + k0 + aSeg * 4);
        if (FROM_AGG) {
            a.x = fmaxf(a.x, 0.f); a.y = fmaxf(a.y, 0.f);
            a.z = fmaxf(a.z, 0.f); a.w = fmaxf(a.w, 0.f);
        }
        As[(aSeg * 4 + 0) * BM + aRow] = a.x;
        As[(aSeg * 4 + 1) * BM + aRow] = a.y;
        As[(aSeg * 4 + 2) * BM + aRow] = a.z;
        As[(aSeg * 4 + 3) * BM + aRow] = a.w;

        if (BN == 128 || tid < (BK * BN / 4)) {
            int bRow = tid / (BN / 4);
            int bCol = (tid % (BN / 4)) * 4;
            float4 b = *(const float4*)(W + (size_t)(k0 + bRow) * BN + bCol);
            *(float4*)&Bs[bRow * BN + bCol] = b;
        }
        __syncthreads();

#pragma unroll
        for (int kk = 0; kk < BK; kk++) {
            float ra[TM], rb[TN];
#pragma unroll
            for (int i = 0; i < TM; i++) ra[i] = As[kk * BM + tRow * TM + i];
#pragma unroll
            for (int j = 0; j < TN; j++) rb[j] = Bs[kk * BN + tCol * TN + j];
#pragma unroll
            for (int i = 0; i < TM; i++)
#pragma unroll
                for (int j = 0; j < TN; j++) acc[i][j] += ra[i] * rb[j];
        }
        __syncthreads();
    }

#pragma unroll
    for (int i = 0; i < TM; i++) {
        int gr = br + tRow * TM + i;
        if (gr < M) {
            float* out = g_h + (size_t)gr * BN + tCol * TN;
#pragma unroll
            for (int j = 0; j < TN; j++) out[j] = acc[i][j];
        }
    }
}

// --------------------- gather aggregation (F=128) ---------------------------
// one warp per node; lane owns one float4 (32 lanes * 4 = 128 features)
__global__ void k_aggregate128(const float* __restrict__ bias, int n) {
    int node = (int)(((size_t)blockIdx.x * blockDim.x + threadIdx.x) >> 5);
    int lane = threadIdx.x & 31;
    if (node >= n) return;

    const float4* __restrict__ h4 = (const float4*)g_h;
    float disd = g_dis[node];

    // bias + self loop
    float4 acc = ((const float4*)bias)[lane];
    {
        float nrm = disd * disd;
        float4 v = h4[(size_t)node * 32 + lane];
        acc.x += v.x * nrm; acc.y += v.y * nrm;
        acc.z += v.z * nrm; acc.w += v.w * nrm;
    }

    int e = g_rowptr[node];
    int end = g_rowptr[node + 1];
    for (; e + 1 < end; e += 2) {
        int s0 = g_esrc[e], s1 = g_esrc[e + 1];
        float n0 = g_dis[s0] * disd, n1 = g_dis[s1] * disd;
        float4 v0 = h4[(size_t)s0 * 32 + lane];
        float4 v1 = h4[(size_t)s1 * 32 + lane];
        acc.x += v0.x * n0 + v1.x * n1;
        acc.y += v0.y * n0 + v1.y * n1;
        acc.z += v0.z * n0 + v1.z * n1;
        acc.w += v0.w * n0 + v1.w * n1;
    }
    if (e < end) {
        int s0 = g_esrc[e];
        float n0 = g_dis[s0] * disd;
        float4 v0 = h4[(size_t)s0 * 32 + lane];
        acc.x += v0.x * n0; acc.y += v0.y * n0;
        acc.z += v0.z * n0; acc.w += v0.w * n0;
    }

    ((float4*)g_agg)[(size_t)node * 32 + lane] = acc;
}

// ------- gather aggregation (F=64) fused with relu + log_softmax ------------
__global__ void k_aggregate64_softmax(const float* __restrict__ bias,
                                      float* __restrict__ out, int n) {
    int node = (int)(((size_t)blockIdx.x * blockDim.x + threadIdx.x) >> 5);
    int lane = threadIdx.x & 31;
    if (node >= n) return;

    const float2* __restrict__ h2 = (const float2*)g_h;
    float disd = g_dis[node];

    float2 acc = ((const float2*)bias)[lane];
    {
        float nrm = disd * disd;
        float2 v = h2[(size_t)node * 32 + lane];
        acc.x += v.x * nrm; acc.y += v.y * nrm;
    }

    int e = g_rowptr[node];
    int end = g_rowptr[node + 1];
    for (; e + 1 < end; e += 2) {
        int s0 = g_esrc[e], s1 = g_esrc[e + 1];
        float n0 = g_dis[s0] * disd, n1 = g_dis[s1] * disd;
        float2 v0 = h2[(size_t)s0 * 32 + lane];
        float2 v1 = h2[(size_t)s1 * 32 + lane];
        acc.x += v0.x * n0 + v1.x * n1;
        acc.y += v0.y * n0 + v1.y * n1;
    }
    if (e < end) {
        int s0 = g_esrc[e];
        float n0 = g_dis[s0] * disd;
        float2 v0 = h2[(size_t)s0 * 32 + lane];
        acc.x += v0.x * n0; acc.y += v0.y * n0;
    }

    // relu + log_softmax over the 64 values held across the warp
    acc.x = fmaxf(acc.x, 0.f);
    acc.y = fmaxf(acc.y, 0.f);

    float m = fmaxf(acc.x, acc.y);
#pragma unroll
    for (int off = 16; off; off >>= 1) m = fmaxf(m, __shfl_xor_sync(0xFFFFFFFFu, m, off));

    float ssum = expf(acc.x - m) + expf(acc.y - m);
#pragma unroll
    for (int off = 16; off; off >>= 1) ssum += __shfl_xor_sync(0xFFFFFFFFu, ssum, off);

    float l = logf(ssum);
    float2 o;
    o.x = acc.x - m - l;
    o.y = acc.y - m - l;
    ((float2*)out)[(size_t)node * 32 + lane] = o;
}

// ----------------------------------------------------------------------------
extern "C" void kernel_launch(void* const* d_in, const int* in_sizes, int n_in,
                              void* d_out, int out_size) {
    const float* x  = (const float*)d_in[0];
    const int* ei   = (const int*)d_in[1];
    const float* W0 = (const float*)d_in[2];
    const float* b0 = (const float*)d_in[3];
    const float* W1 = (const float*)d_in[4];
    const float* b1 = (const float*)d_in[5];
    const float* W2 = (const float*)d_in[6];
    const float* b2 = (const float*)d_in[7];
    float* out = (float*)d_out;

    const int N = in_sizes[0] / 128;
    const int E = in_sizes[1] / 2;
    const int* src = ei;
    const int* dst = ei + E;

    const int T = 256;

    // degree + CSR build
    k_deg_init<<<(N + T - 1) / T, T>>>(N);
    k_deg_count<<<(E + T - 1) / T, T>>>(dst, E);
    k_deg_rsqrt<<<(N + T - 1) / T, T>>>(N);
    k_scan<<<1, 1024>>>(N);
    k_fill<<<(E + T - 1) / T, T>>>(src, dst, E);

    const int gemmBlocks = (N + 127) / 128;
    const int aggBlocks = (N * 32 + T - 1) / T;

    // ---- layer 0: 128 -> 128
    k_gemm<128, 8, false><<<gemmBlocks, 256>>>(x, W0, N);
    k_aggregate128<<<aggBlocks, T>>>(b0, N);

    // ---- layer 1: 128 -> 128 (relu fused into GEMM A load)
    k_gemm<128, 8, true><<<gemmBlocks, 256>>>(nullptr, W1, N);
    k_aggregate128<<<aggBlocks, T>>>(b1, N);

    // ---- layer 2: 128 -> 64, aggregation fused with relu + log_softmax
    k_gemm<64, 4, true><<<gemmBlocks, 256>>>(nullptr, W2, N);
    k_aggregate64_softmax<<<aggBlocks, T>>>(b2, out, N);
}

// round 6
// speedup vs baseline: 1.7279x; 1.1703x over previous
#include <cuda_runtime.h>
#include <cuda_bf16.h>
#include <cstdint>

// ---------------------------------------------------------------------------
// FCHCGNN: 3-layer GCN, CSR gather formulation (no float atomics).
// ---------------------------------------------------------------------------

#define MAXN 100000
#define MAXE 1600000
#define FDIM 128

__device__ float g_h[(size_t)MAXN * FDIM];    // GEMM output (message source)
__device__ float g_agg[(size_t)MAXN * FDIM];  // aggregation buffer
__device__ float g_dis[MAXN];                 // rsqrt(deg)
__device__ int   g_cnt[MAXN];                 // in-degree counts
__device__ int   g_cur[MAXN];                 // fill cursors
__device__ int   g_rowptr[MAXN + 1];          // CSR row pointers (by dst)
__device__ int   g_esrc[MAXE];                // CSR: src node per slot
__device__ int   g_bsum[128];                 // per-block scan sums
__device__ int   g_boff[130];                 // scanned block offsets (+total)

// ------------------------------- degree ------------------------------------
__global__ void k_deg_init(int n) {
    int i = blockIdx.x * blockDim.x + threadIdx.x;
    if (i < n) { g_cnt[i] = 0; g_cur[i] = 0; }
}

__global__ void k_deg_count(const int* __restrict__ dst, int E) {
    int e = blockIdx.x * blockDim.x + threadIdx.x;
    if (e < E) atomicAdd(&g_cnt[dst[e]], 1);
}

__global__ void k_deg_rsqrt(int n) {
    int i = blockIdx.x * blockDim.x + threadIdx.x;
    if (i < n) g_dis[i] = rsqrtf(1.0f + (float)g_cnt[i]);  // +1 self loop
}

// ----------------------- hierarchical exclusive scan ------------------------
// phase 1: per-block (1024 elems) shuffle scan, local-exclusive to rowptr
__global__ void k_scan_local(int n) {
    const int tid = threadIdx.x, lane = tid & 31, wid = tid >> 5;
    const int i = blockIdx.x * 1024 + tid;
    int v = (i < n) ? g_cnt[i] : 0;

    int s = v;
#pragma unroll
    for (int off = 1; off < 32; off <<= 1) {
        int t = __shfl_up_sync(0xFFFFFFFFu, s, off);
        if (lane >= off) s += t;
    }
    __shared__ int wsum[32];
    if (lane == 31) wsum[wid] = s;
    __syncthreads();
    if (wid == 0) {
        int w = wsum[lane];
#pragma unroll
        for (int off = 1; off < 32; off <<= 1) {
            int t = __shfl_up_sync(0xFFFFFFFFu, w, off);
            if (lane >= off) w += t;
        }
        wsum[lane] = w;
    }
    __syncthreads();
    int base = wid ? wsum[wid - 1] : 0;
    int incl = base + s;
    if (i < n) g_rowptr[i] = incl - v;         // block-local exclusive
    if (tid == 1023) g_bsum[blockIdx.x] = incl; // block total
}

// phase 2: scan the (<=128) block sums with one block
__global__ void k_scan_bsums(int nb) {
    const int tid = threadIdx.x, lane = tid & 31, wid = tid >> 5;
    int v = (tid < nb) ? g_bsum[tid] : 0;
    int s = v;
#pragma unroll
    for (int off = 1; off < 32; off <<= 1) {
        int t = __shfl_up_sync(0xFFFFFFFFu, s, off);
        if (lane >= off) s += t;
    }
    __shared__ int wsum[4];
    if (lane == 31) wsum[wid] = s;
    __syncthreads();
    int base = 0;
    for (int w = 0; w < wid; w++) base += wsum[w];
    int incl = base + s;
    if (tid < nb) g_boff[tid] = incl - v;      // exclusive
    if (tid == 127) g_boff[nb] = incl;          // grand total (pads are 0)
}

// phase 3: add block offsets; set rowptr[n]
__global__ void k_scan_add(int n, int nb) {
    int i = blockIdx.x * 1024 + threadIdx.x;
    if (i < n) g_rowptr[i] += g_boff[blockIdx.x];
    if (i == 0) g_rowptr[n] = g_boff[nb];
}

// ------------------------------ CSR fill ------------------------------------
__global__ void k_fill(const int* __restrict__ src, const int* __restrict__ dst, int E) {
    int e = blockIdx.x * blockDim.x + threadIdx.x;
    if (e < E) {
        int d = dst[e];
        int pos = g_rowptr[d] + atomicAdd(&g_cur[d], 1);
        g_esrc[pos] = src[e];
    }
}

// ------------------------------- GEMM ---------------------------------------
// H[M,BN] = relu?(X[M,128]) @ W[128,BN].  BM=128, BK=8, TM=8, double-buffered.
template <int BN, int TN, bool FROM_AGG>
__global__ void k_gemm(const float* __restrict__ Xin, const float* __restrict__ W, int M) {
    constexpr int BM = 128, BK = 8, TM = 8, K = 128;
    __shared__ float As[2][BK * BM];
    __shared__ float Bs[2][BK * BN];

    const float* __restrict__ X = FROM_AGG ? g_agg : Xin;

    const int tid = threadIdx.x;
    const int br = blockIdx.x * BM;
    const int tCol = tid % (BN / TN);
    const int tRow = tid / (BN / TN);

    const int aRow = tid >> 1;       // 0..127
    const int aSeg = tid & 1;        // which float4 of the 8-wide k slice
    const bool bAct = (BN == 128) || (tid < (BK * BN / 4));
    const int bRow = tid / (BN / 4);
    const int bCol = (tid % (BN / 4)) * 4;
    const int gr = br + aRow;

    float acc[TM][TN];
#pragma unroll
    for (int i = 0; i < TM; i++)
#pragma unroll
        for (int j = 0; j < TN; j++) acc[i][j] = 0.0f;

    // ---- load first tile
    float4 aP = make_float4(0.f, 0.f, 0.f, 0.f);
    float4 bP = make_float4(0.f, 0.f, 0.f, 0.f);
    if (gr < M) aP = *(const float4*)(X + (size_t)gr * K + aSeg * 4);
    if (bAct)   bP = *(const float4*)(W + (size_t)bRow * BN + bCol);
    if (FROM_AGG) {
        aP.x = fmaxf(aP.x, 0.f); aP.y = fmaxf(aP.y, 0.f);
        aP.z = fmaxf(aP.z, 0.f); aP.w = fmaxf(aP.w, 0.f);
    }
    As[0][(aSeg * 4 + 0) * BM + aRow] = aP.x;
    As[0][(aSeg * 4 + 1) * BM + aRow] = aP.y;
    As[0][(aSeg * 4 + 2) * BM + aRow] = aP.z;
    As[0][(aSeg * 4 + 3) * BM + aRow] = aP.w;
    if (bAct) *(float4*)&Bs[0][bRow * BN + bCol] = bP;
    __syncthreads();

    int buf = 0;
#pragma unroll
    for (int k0 = 0; k0 < K; k0 += BK) {
        const int nk = k0 + BK;
        if (nk < K) {
            aP = make_float4(0.f, 0.f, 0.f, 0.f);
            if (gr < M) aP = *(const float4*)(X + (size_t)gr * K + nk + aSeg * 4);
            if (bAct)   bP = *(const float4*)(W + (size_t)(nk + bRow) * BN + bCol);
            if (FROM_AGG) {
                aP.x = fmaxf(aP.x, 0.f); aP.y = fmaxf(aP.y, 0.f);
                aP.z = fmaxf(aP.z, 0.f); aP.w = fmaxf(aP.w, 0.f);
            }
        }

#pragma unroll
        for (int kk = 0; kk < BK; kk++) {
            float ra[TM], rb[TN];
#pragma unroll
            for (int i = 0; i < TM; i++) ra[i] = As[buf][kk * BM + tRow * TM + i];
#pragma unroll
            for (int j = 0; j < TN; j++) rb[j] = Bs[buf][kk * BN + tCol * TN + j];
#pragma unroll
            for (int i = 0; i < TM; i++)
#pragma unroll
                for (int j = 0; j < TN; j++) acc[i][j] += ra[i] * rb[j];
        }

        if (nk < K) {
            const int nb = buf ^ 1;
            As[nb][(aSeg * 4 + 0) * BM + aRow] = aP.x;
            As[nb][(aSeg * 4 + 1) * BM + aRow] = aP.y;
            As[nb][(aSeg * 4 + 2) * BM + aRow] = aP.z;
            As[nb][(aSeg * 4 + 3) * BM + aRow] = aP.w;
            if (bAct) *(float4*)&Bs[nb][bRow * BN + bCol] = bP;
            __syncthreads();
            buf = nb;
        }
    }

#pragma unroll
    for (int i = 0; i < TM; i++) {
        int grr = br + tRow * TM + i;
        if (grr < M) {
            float* out = g_h + (size_t)grr * BN + tCol * TN;
#pragma unroll
            for (int j = 0; j < TN; j++) out[j] = acc[i][j];
        }
    }
}

// --------------------- gather aggregation (F=128) ---------------------------
// one warp per node; lane owns one float4 (32 lanes * 4 = 128 features)
__global__ void k_aggregate128(const float* __restrict__ bias, int n) {
    int node = (int)(((size_t)blockIdx.x * blockDim.x + threadIdx.x) >> 5);
    int lane = threadIdx.x & 31;
    if (node >= n) return;

    const float4* __restrict__ h4 = (const float4*)g_h;
    float disd = g_dis[node];

    float4 acc = ((const float4*)bias)[lane];
    {
        float nrm = disd * disd;
        float4 v = h4[(size_t)node * 32 + lane];
        acc.x += v.x * nrm; acc.y += v.y * nrm;
        acc.z += v.z * nrm; acc.w += v.w * nrm;
    }

    int e = g_rowptr[node];
    int end = g_rowptr[node + 1];
    for (; e + 1 < end; e += 2) {
        int s0 = g_esrc[e], s1 = g_esrc[e + 1];
        float n0 = g_dis[s0] * disd, n1 = g_dis[s1] * disd;
        float4 v0 = h4[(size_t)s0 * 32 + lane];
        float4 v1 = h4[(size_t)s1 * 32 + lane];
        acc.x += v0.x * n0 + v1.x * n1;
        acc.y += v0.y * n0 + v1.y * n1;
        acc.z += v0.z * n0 + v1.z * n1;
        acc.w += v0.w * n0 + v1.w * n1;
    }
    if (e < end) {
        int s0 = g_esrc[e];
        float n0 = g_dis[s0] * disd;
        float4 v0 = h4[(size_t)s0 * 32 + lane];
        acc.x += v0.x * n0; acc.y += v0.y * n0;
        acc.z += v0.z * n0; acc.w += v0.w * n0;
    }

    ((float4*)g_agg)[(size_t)node * 32 + lane] = acc;
}

// ------- gather aggregation (F=64) fused with relu + log_softmax ------------
__global__ void k_aggregate64_softmax(const float* __restrict__ bias,
                                      float* __restrict__ out, int n) {
    int node = (int)(((size_t)blockIdx.x * blockDim.x + threadIdx.x) >> 5);
    int lane = threadIdx.x & 31;
    if (node >= n) return;

    const float2* __restrict__ h2 = (const float2*)g_h;
    float disd = g_dis[node];

    float2 acc = ((const float2*)bias)[lane];
    {
        float nrm = disd * disd;
        float2 v = h2[(size_t)node * 32 + lane];
        acc.x += v.x * nrm; acc.y += v.y * nrm;
    }

    int e = g_rowptr[node];
    int end = g_rowptr[node + 1];
    for (; e + 1 < end; e += 2) {
        int s0 = g_esrc[e], s1 = g_esrc[e + 1];
        float n0 = g_dis[s0] * disd, n1 = g_dis[s1] * disd;
        float2 v0 = h2[(size_t)s0 * 32 + lane];
        float2 v1 = h2[(size_t)s1 * 32 + lane];
        acc.x += v0.x * n0 + v1.x * n1;
        acc.y += v0.y * n0 + v1.y * n1;
    }
    if (e < end) {
        int s0 = g_esrc[e];
        float n0 = g_dis[s0] * disd;
        float2 v0 = h2[(size_t)s0 * 32 + lane];
        acc.x += v0.x * n0; acc.y += v0.y * n0;
    }

    acc.x = fmaxf(acc.x, 0.f);
    acc.y = fmaxf(acc.y, 0.f);

    float m = fmaxf(acc.x, acc.y);
#pragma unroll
    for (int off = 16; off; off >>= 1) m = fmaxf(m, __shfl_xor_sync(0xFFFFFFFFu, m, off));

    float ssum = expf(acc.x - m) + expf(acc.y - m);
#pragma unroll
    for (int off = 16; off; off >>= 1) ssum += __shfl_xor_sync(0xFFFFFFFFu, ssum, off);

    float l = logf(ssum);
    float2 o;
    o.x = acc.x - m - l;
    o.y = acc.y - m - l;
    ((float2*)out)[(size_t)node * 32 + lane] = o;
}

// ----------------------------------------------------------------------------
extern "C" void kernel_launch(void* const* d_in, const int* in_sizes, int n_in,
                              void* d_out, int out_size) {
    const float* x  = (const float*)d_in[0];
    const int* ei   = (const int*)d_in[1];
    const float* W0 = (const float*)d_in[2];
    const float* b0 = (const float*)d_in[3];
    const float* W1 = (const float*)d_in[4];
    const float* b1 = (const float*)d_in[5];
    const float* W2 = (const float*)d_in[6];
    const float* b2 = (const float*)d_in[7];
    float* out = (float*)d_out;

    const int N = in_sizes[0] / 128;
    const int E = in_sizes[1] / 2;
    const int* src = ei;
    const int* dst = ei + E;

    const int T = 256;
    const int nb = (N + 1023) / 1024;

    // degree + CSR build
    k_deg_init<<<(N + T - 1) / T, T>>>(N);
    k_deg_count<<<(E + T - 1) / T, T>>>(dst, E);
    k_deg_rsqrt<<<(N + T - 1) / T, T>>>(N);
    k_scan_local<<<nb, 1024>>>(N);
    k_scan_bsums<<<1, 128>>>(nb);
    k_scan_add<<<nb, 1024>>>(N, nb);
    k_fill<<<(E + T - 1) / T, T>>>(src, dst, E);

    const int gemmBlocks = (N + 127) / 128;
    const int aggBlocks = (N * 32 + T - 1) / T;

    // ---- layer 0: 128 -> 128
    k_gemm<128, 8, false><<<gemmBlocks, 256>>>(x, W0, N);
    k_aggregate128<<<aggBlocks, T>>>(b0, N);

    // ---- layer 1: 128 -> 128 (relu fused into GEMM A load)
    k_gemm<128, 8, true><<<gemmBlocks, 256>>>(nullptr, W1, N);
    k_aggregate128<<<aggBlocks, T>>>(b1, N);

    // ---- layer 2: 128 -> 64, aggregation fused with relu + log_softmax
    k_gemm<64, 4, true><<<gemmBlocks, 256>>>(nullptr, W2, N);
    k_aggregate64_softmax<<<aggBlocks, T>>>(b2, out, N);
}

// round 7
// speedup vs baseline: 2.3226x; 1.3442x over previous
#include <cuda_runtime.h>
#include <cuda_bf16.h>
#include <cstdint>

// ---------------------------------------------------------------------------
// FCHCGNN: 3-layer GCN, CSR gather formulation (no float atomics).
// CSR build overlapped with layer-0 GEMM via stream fork/join (graph-safe).
// ---------------------------------------------------------------------------

#define MAXN 100000
#define MAXE 1600000
#define FDIM 128

__device__ float g_h[(size_t)MAXN * FDIM];    // GEMM output (message source)
__device__ float g_agg[(size_t)MAXN * FDIM];  // aggregation buffer
__device__ float g_dis[MAXN];                 // rsqrt(deg)
__device__ int   g_cnt[MAXN];                 // in-degree counts
__device__ int   g_cur[MAXN];                 // fill cursors
__device__ int   g_rowptr[MAXN + 1];          // CSR row pointers (by dst)
__device__ int   g_esrc[MAXE];                // CSR: src node per slot
__device__ int   g_bsum[128];                 // per-block scan sums
__device__ int   g_boff[130];                 // scanned block offsets (+total)

// ------------------------------- degree ------------------------------------
__global__ void k_deg_init(int n) {
    int i = blockIdx.x * blockDim.x + threadIdx.x;
    if (i < n) { g_cnt[i] = 0; g_cur[i] = 0; }
}

__global__ void k_deg_count(const int* __restrict__ dst, int E) {
    int e = blockIdx.x * blockDim.x + threadIdx.x;
    if (e < E) atomicAdd(&g_cnt[dst[e]], 1);
}

__global__ void k_deg_rsqrt(int n) {
    int i = blockIdx.x * blockDim.x + threadIdx.x;
    if (i < n) g_dis[i] = rsqrtf(1.0f + (float)g_cnt[i]);  // +1 self loop
}

// ----------------------- hierarchical exclusive scan ------------------------
__global__ void k_scan_local(int n) {
    const int tid = threadIdx.x, lane = tid & 31, wid = tid >> 5;
    const int i = blockIdx.x * 1024 + tid;
    int v = (i < n) ? g_cnt[i] : 0;

    int s = v;
#pragma unroll
    for (int off = 1; off < 32; off <<= 1) {
        int t = __shfl_up_sync(0xFFFFFFFFu, s, off);
        if (lane >= off) s += t;
    }
    __shared__ int wsum[32];
    if (lane == 31) wsum[wid] = s;
    __syncthreads();
    if (wid == 0) {
        int w = wsum[lane];
#pragma unroll
        for (int off = 1; off < 32; off <<= 1) {
            int t = __shfl_up_sync(0xFFFFFFFFu, w, off);
            if (lane >= off) w += t;
        }
        wsum[lane] = w;
    }
    __syncthreads();
    int base = wid ? wsum[wid - 1] : 0;
    int incl = base + s;
    if (i < n) g_rowptr[i] = incl - v;
    if (tid == 1023) g_bsum[blockIdx.x] = incl;
}

__global__ void k_scan_bsums(int nb) {
    const int tid = threadIdx.x, lane = tid & 31, wid = tid >> 5;
    int v = (tid < nb) ? g_bsum[tid] : 0;
    int s = v;
#pragma unroll
    for (int off = 1; off < 32; off <<= 1) {
        int t = __shfl_up_sync(0xFFFFFFFFu, s, off);
        if (lane >= off) s += t;
    }
    __shared__ int wsum[4];
    if (lane == 31) wsum[wid] = s;
    __syncthreads();
    int base = 0;
    for (int w = 0; w < wid; w++) base += wsum[w];
    int incl = base + s;
    if (tid < nb) g_boff[tid] = incl - v;
    if (tid == 127) g_boff[nb] = incl;
}

__global__ void k_scan_add(int n, int nb) {
    int i = blockIdx.x * 1024 + threadIdx.x;
    if (i < n) g_rowptr[i] += g_boff[blockIdx.x];
    if (i == 0) g_rowptr[n] = g_boff[nb];
}

// ------------------------------ CSR fill ------------------------------------
__global__ void k_fill(const int* __restrict__ src, const int* __restrict__ dst, int E) {
    int e = blockIdx.x * blockDim.x + threadIdx.x;
    if (e < E) {
        int d = dst[e];
        int pos = g_rowptr[d] + atomicAdd(&g_cur[d], 1);
        g_esrc[pos] = src[e];
    }
}

// ------------------------------- GEMM ---------------------------------------
// H[M,BN] = relu?(X[M,128]) @ W[128,BN].
// 512 threads, BM=128, BK=16, TN=4, double buffered.
// tRow is warp-uniform -> A-fragment LDS are broadcasts; B reads conflict-free.
template <int BN, int TM, bool FROM_AGG>
__global__ void __launch_bounds__(512, 2)
k_gemm(const float* __restrict__ Xin, const float* __restrict__ W, int M) {
    constexpr int BM = 128, BK = 16, TN = 4, K = 128, NTH = 512;
    __shared__ float As[2][BK * BM];
    __shared__ float Bs[2][BK * BN];

    const float* __restrict__ X = FROM_AGG ? g_agg : Xin;

    const int tid = threadIdx.x;
    const int br = blockIdx.x * BM;
    const int tCol = tid % (BN / TN);
    const int tRow = tid / (BN / TN);

    const int aRow = tid >> 2;           // 0..127
    const int aSeg = tid & 3;            // float4 within 16-wide k slice
    constexpr int B_THREADS = BK * BN / 4;
    const bool bAct = (B_THREADS == NTH) || (tid < B_THREADS);
    const int bRow = tid / (BN / 4);
    const int bCol = (tid % (BN / 4)) * 4;
    const int gr = br + aRow;

    float acc[TM][TN];
#pragma unroll
    for (int i = 0; i < TM; i++)
#pragma unroll
        for (int j = 0; j < TN; j++) acc[i][j] = 0.0f;

    // ---- prologue: tile 0
    float4 aP = make_float4(0.f, 0.f, 0.f, 0.f);
    float4 bP = make_float4(0.f, 0.f, 0.f, 0.f);
    if (gr < M) aP = *(const float4*)(X + (size_t)gr * K + aSeg * 4);
    if (bAct)   bP = *(const float4*)(W + (size_t)bRow * BN + bCol);
    if (FROM_AGG) {
        aP.x = fmaxf(aP.x, 0.f); aP.y = fmaxf(aP.y, 0.f);
        aP.z = fmaxf(aP.z, 0.f); aP.w = fmaxf(aP.w, 0.f);
    }
    As[0][(aSeg * 4 + 0) * BM + aRow] = aP.x;
    As[0][(aSeg * 4 + 1) * BM + aRow] = aP.y;
    As[0][(aSeg * 4 + 2) * BM + aRow] = aP.z;
    As[0][(aSeg * 4 + 3) * BM + aRow] = aP.w;
    if (bAct) *(float4*)&Bs[0][bRow * BN + bCol] = bP;
    __syncthreads();

    int buf = 0;
#pragma unroll
    for (int k0 = 0; k0 < K; k0 += BK) {
        const int nk = k0 + BK;
        if (nk < K) {
            aP = make_float4(0.f, 0.f, 0.f, 0.f);
            if (gr < M) aP = *(const float4*)(X + (size_t)gr * K + nk + aSeg * 4);
            if (bAct)   bP = *(const float4*)(W + (size_t)(nk + bRow) * BN + bCol);
            if (FROM_AGG) {
                aP.x = fmaxf(aP.x, 0.f); aP.y = fmaxf(aP.y, 0.f);
                aP.z = fmaxf(aP.z, 0.f); aP.w = fmaxf(aP.w, 0.f);
            }
        }

#pragma unroll
        for (int kk = 0; kk < BK; kk++) {
            float ra[TM], rb[TN];
#pragma unroll
            for (int i = 0; i < TM / 4; i++) {
                float4 t = *(const float4*)&As[buf][kk * BM + tRow * TM + i * 4];
                ra[i * 4 + 0] = t.x; ra[i * 4 + 1] = t.y;
                ra[i * 4 + 2] = t.z; ra[i * 4 + 3] = t.w;
            }
            {
                float4 t = *(const float4*)&Bs[buf][kk * BN + tCol * TN];
                rb[0] = t.x; rb[1] = t.y; rb[2] = t.z; rb[3] = t.w;
            }
#pragma unroll
            for (int i = 0; i < TM; i++)
#pragma unroll
                for (int j = 0; j < TN; j++) acc[i][j] += ra[i] * rb[j];
        }

        if (nk < K) {
            const int nxt = buf ^ 1;
            As[nxt][(aSeg * 4 + 0) * BM + aRow] = aP.x;
            As[nxt][(aSeg * 4 + 1) * BM + aRow] = aP.y;
            As[nxt][(aSeg * 4 + 2) * BM + aRow] = aP.z;
            As[nxt][(aSeg * 4 + 3) * BM + aRow] = aP.w;
            if (bAct) *(float4*)&Bs[nxt][bRow * BN + bCol] = bP;
            __syncthreads();
            buf = nxt;
        }
    }

#pragma unroll
    for (int i = 0; i < TM; i++) {
        int grr = br + tRow * TM + i;
        if (grr < M) {
            float4 o = make_float4(acc[i][0], acc[i][1], acc[i][2], acc[i][3]);
            *(float4*)(g_h + (size_t)grr * BN + tCol * TN) = o;
        }
    }
}

// --------------------- gather aggregation (F=128) ---------------------------
__global__ void k_aggregate128(const float* __restrict__ bias, int n) {
    int node = (int)(((size_t)blockIdx.x * blockDim.x + threadIdx.x) >> 5);
    int lane = threadIdx.x & 31;
    if (node >= n) return;

    const float4* __restrict__ h4 = (const float4*)g_h;
    float disd = g_dis[node];

    float4 acc = ((const float4*)bias)[lane];
    {
        float nrm = disd * disd;
        float4 v = h4[(size_t)node * 32 + lane];
        acc.x += v.x * nrm; acc.y += v.y * nrm;
        acc.z += v.z * nrm; acc.w += v.w * nrm;
    }

    int e = g_rowptr[node];
    int end = g_rowptr[node + 1];
    for (; e + 3 < end; e += 4) {
        int s0 = g_esrc[e],     s1 = g_esrc[e + 1];
        int s2 = g_esrc[e + 2], s3 = g_esrc[e + 3];
        float n0 = g_dis[s0] * disd, n1 = g_dis[s1] * disd;
        float n2 = g_dis[s2] * disd, n3 = g_dis[s3] * disd;
        float4 v0 = h4[(size_t)s0 * 32 + lane];
        float4 v1 = h4[(size_t)s1 * 32 + lane];
        float4 v2 = h4[(size_t)s2 * 32 + lane];
        float4 v3 = h4[(size_t)s3 * 32 + lane];
        acc.x += v0.x * n0 + v1.x * n1 + v2.x * n2 + v3.x * n3;
        acc.y += v0.y * n0 + v1.y * n1 + v2.y * n2 + v3.y * n3;
        acc.z += v0.z * n0 + v1.z * n1 + v2.z * n2 + v3.z * n3;
        acc.w += v0.w * n0 + v1.w * n1 + v2.w * n2 + v3.w * n3;
    }
    for (; e < end; e++) {
        int s0 = g_esrc[e];
        float n0 = g_dis[s0] * disd;
        float4 v0 = h4[(size_t)s0 * 32 + lane];
        acc.x += v0.x * n0; acc.y += v0.y * n0;
        acc.z += v0.z * n0; acc.w += v0.w * n0;
    }

    ((float4*)g_agg)[(size_t)node * 32 + lane] = acc;
}

// ------- gather aggregation (F=64) fused with relu + log_softmax ------------
__global__ void k_aggregate64_softmax(const float* __restrict__ bias,
                                      float* __restrict__ out, int n) {
    int node = (int)(((size_t)blockIdx.x * blockDim.x + threadIdx.x) >> 5);
    int lane = threadIdx.x & 31;
    if (node >= n) return;

    const float2* __restrict__ h2 = (const float2*)g_h;
    float disd = g_dis[node];

    float2 acc = ((const float2*)bias)[lane];
    {
        float nrm = disd * disd;
        float2 v = h2[(size_t)node * 32 + lane];
        acc.x += v.x * nrm; acc.y += v.y * nrm;
    }

    int e = g_rowptr[node];
    int end = g_rowptr[node + 1];
    for (; e + 3 < end; e += 4) {
        int s0 = g_esrc[e],     s1 = g_esrc[e + 1];
        int s2 = g_esrc[e + 2], s3 = g_esrc[e + 3];
        float n0 = g_dis[s0] * disd, n1 = g_dis[s1] * disd;
        float n2 = g_dis[s2] * disd, n3 = g_dis[s3] * disd;
        float2 v0 = h2[(size_t)s0 * 32 + lane];
        float2 v1 = h2[(size_t)s1 * 32 + lane];
        float2 v2 = h2[(size_t)s2 * 32 + lane];
        float2 v3 = h2[(size_t)s3 * 32 + lane];
        acc.x += v0.x * n0 + v1.x * n1 + v2.x * n2 + v3.x * n3;
        acc.y += v0.y * n0 + v1.y * n1 + v2.y * n2 + v3.y * n3;
    }
    for (; e < end; e++) {
        int s0 = g_esrc[e];
        float n0 = g_dis[s0] * disd;
        float2 v0 = h2[(size_t)s0 * 32 + lane];
        acc.x += v0.x * n0; acc.y += v0.y * n0;
    }

    acc.x = fmaxf(acc.x, 0.f);
    acc.y = fmaxf(acc.y, 0.f);

    float m = fmaxf(acc.x, acc.y);
#pragma unroll
    for (int off = 16; off; off >>= 1) m = fmaxf(m, __shfl_xor_sync(0xFFFFFFFFu, m, off));

    float ssum = expf(acc.x - m) + expf(acc.y - m);
#pragma unroll
    for (int off = 16; off; off >>= 1) ssum += __shfl_xor_sync(0xFFFFFFFFu, ssum, off);

    float l = logf(ssum);
    float2 o;
    o.x = acc.x - m - l;
    o.y = acc.y - m - l;
    ((float2*)out)[(size_t)node * 32 + lane] = o;
}

// ----------------------------------------------------------------------------
extern "C" void kernel_launch(void* const* d_in, const int* in_sizes, int n_in,
                              void* d_out, int out_size) {
    const float* x  = (const float*)d_in[0];
    const int* ei   = (const int*)d_in[1];
    const float* W0 = (const float*)d_in[2];
    const float* b0 = (const float*)d_in[3];
    const float* W1 = (const float*)d_in[4];
    const float* b1 = (const float*)d_in[5];
    const float* W2 = (const float*)d_in[6];
    const float* b2 = (const float*)d_in[7];
    float* out = (float*)d_out;

    const int N = in_sizes[0] / 128;
    const int E = in_sizes[1] / 2;
    const int* src = ei;
    const int* dst = ei + E;

    const int T = 256;
    const int nb = (N + 1023) / 1024;

    // one-time side stream + events (created on the uncaptured correctness
    // call; same launch structure every call)
    static cudaStream_t s_side = nullptr;
    static cudaEvent_t ev_fork = nullptr, ev_csr = nullptr;
    if (s_side == nullptr) {
        cudaStreamCreateWithFlags(&s_side, cudaStreamNonBlocking);
        cudaEventCreateWithFlags(&ev_fork, cudaEventDisableTiming);
        cudaEventCreateWithFlags(&ev_csr, cudaEventDisableTiming);
    }

    // ---- fork: CSR build on side stream, GEMM-0 on main stream
    cudaEventRecord(ev_fork, 0);
    cudaStreamWaitEvent(s_side, ev_fork, 0);

    k_deg_init<<<(N + T - 1) / T, T, 0, s_side>>>(N);
    k_deg_count<<<(E + T - 1) / T, T, 0, s_side>>>(dst, E);
    k_deg_rsqrt<<<(N + T - 1) / T, T, 0, s_side>>>(N);
    k_scan_local<<<nb, 1024, 0, s_side>>>(N);
    k_scan_bsums<<<1, 128, 0, s_side>>>(nb);
    k_scan_add<<<nb, 1024, 0, s_side>>>(N, nb);
    k_fill<<<(E + T - 1) / T, T, 0, s_side>>>(src, dst, E);
    cudaEventRecord(ev_csr, s_side);

    const int gemmBlocks = (N + 127) / 128;
    const int aggBlocks = (N * 32 + T - 1) / T;

    // ---- layer 0: 128 -> 128 (GEMM runs concurrent with CSR build)
    k_gemm<128, 8, false><<<gemmBlocks, 512>>>(x, W0, N);

    cudaStreamWaitEvent(0, ev_csr, 0);   // join: aggregation needs CSR + dis

    k_aggregate128<<<aggBlocks, T>>>(b0, N);

    // ---- layer 1: 128 -> 128 (relu fused into GEMM A load)
    k_gemm<128, 8, true><<<gemmBlocks, 512>>>(nullptr, W1, N);
    k_aggregate128<<<aggBlocks, T>>>(b1, N);

    // ---- layer 2: 128 -> 64, aggregation fused with relu + log_softmax
    k_gemm<64, 4, true><<<gemmBlocks, 512>>>(nullptr, W2, N);
    k_aggregate64_softmax<<<aggBlocks, T>>>(b2, out, N);
}